// round 15
// baseline (speedup 1.0000x reference)
#include <cuda_runtime.h>
#include <cuda_fp16.h>

#define NATOM 100000
#define MNBR  12
#define AF    64
#define BF    41
#define TWOA  128
#define NM    (NATOM*MNBR)          // 1200000
#define NMF   ((double)NM)
#define NF    ((double)NATOM)
#define EPSBN 1e-5
#define NT    (NM/96)               // 12500 tiles
#define PB    148                   // persistent GEMM blocks: 1/SM
#define NTC   (NATOM/32)            // 3125 kC tiles
#define PB_C  592                   // persistent kC blocks

// ---- dynamic smem layout (bytes) for kGemmStore ----
#define OFF_WS    0                              // u32 Ws[48*136]  tf32    = 26112
#define OFF_BT    26112                          // u32 bT[48*104]  tf32    = 19968
#define OFF_BRAW  46080                          // float braw[2][3936]     = 31488
#define OFF_STAG  77568                          // u32 stag[96*65]         = 24960
#define OFF_IDX   102528                         // int idxS[3][96]         = 1152
#define SMEM_BYTES 103680
#define OFF_RED   OFF_STAG                       // stats reduce overlays stag

typedef unsigned long long ull;
typedef unsigned int u32;

// ---------------- scratch (device globals; no allocations) ----------------
__device__ float  d_SW[(size_t)NATOM*TWOA];      // atom @ W[0:64] + bias
__device__ float  d_PW[(size_t)NATOM*TWOA];      // atom @ W[64:128] (fp32)
__device__ u32    d_PWf[(size_t)NATOM*64];       // half2 PW pairs: [atom][j]={PW[2j],PW[2j+1]}
__device__ ull    d_gated16[(size_t)NM*32];      // fp16 gated: [row][l]={f2l,f2l+1,c2l,c2l+1}
__device__ float  d_summed[(size_t)NATOM*AF];
__device__ double d_s1[TWOA], d_q1[TWOA];
__device__ double d_s2[AF],   d_q2[AF];
__device__ float  d_g1[TWOA], d_h1[TWOA];
__device__ float  d_g2[AF],   d_h2[AF];
__device__ unsigned d_c1, d_c2;

// ---------------- helpers ----------------
__device__ __forceinline__ void ffma2(ull &d, ull a, ull b) {
    asm("fma.rn.f32x2 %0, %1, %2, %0;" : "+l"(d) : "l"(a), "l"(b));
}
__device__ __forceinline__ ull packdup(float x) {
    ull r; asm("mov.b64 %0, {%1, %1};" : "=l"(r) : "f"(x)); return r;
}
__device__ __forceinline__ float2 unpk(ull v) {
    float2 r; asm("mov.b64 {%0, %1}, %2;" : "=f"(r.x), "=f"(r.y) : "l"(v)); return r;
}
__device__ __forceinline__ float sigmoidf_(float x) {
    return __fdividef(1.0f, 1.0f + __expf(-x));
}
__device__ __forceinline__ float softplusf_(float x) {
    float e = __expf(-fabsf(x));
    return fmaxf(x, 0.0f) + __logf(1.0f + e);
}
__device__ __forceinline__ void cpasync16(void* dst_smem, const void* src) {
    unsigned s = (unsigned)__cvta_generic_to_shared(dst_smem);
    asm volatile("cp.async.cg.shared.global [%0], [%1], 16;" :: "r"(s), "l"(src) : "memory");
}
#define CP_COMMIT() asm volatile("cp.async.commit_group;" ::: "memory")
#define CP_WAIT(n)  asm volatile("cp.async.wait_group %0;" :: "n"(n) : "memory")

__device__ __forceinline__ u32 to_tf32(float v) {
    u32 u; asm("cvt.rna.tf32.f32 %0, %1;" : "=r"(u) : "f"(v)); return u;
}
#define MMA_TF32(d, a0, a1, a2, a3, b0, b1) \
    asm volatile("mma.sync.aligned.m16n8k8.row.col.f32.tf32.tf32.f32 " \
        "{%0,%1,%2,%3}, {%4,%5,%6,%7}, {%8,%9}, {%0,%1,%2,%3};" \
        : "+f"(d[0]), "+f"(d[1]), "+f"(d[2]), "+f"(d[3]) \
        : "r"(a0), "r"(a1), "r"(a2), "r"(a3), "r"(b0), "r"(b1))

// ---------------- kInit ----------------
__global__ void kInit() {
    int t = threadIdx.x;
    if (t < TWOA) { d_s1[t] = 0.0; d_q1[t] = 0.0; }
    if (t < AF)   { d_s2[t] = 0.0; d_q2[t] = 0.0; }
    if (t == 0)   { d_c1 = 0u; d_c2 = 0u; }
}

// ---------------- kA: SW = atom@W1 + b, PW = atom@W2 ----------------
__global__ void __launch_bounds__(256) kA(const float* __restrict__ atom,
                                          const float* __restrict__ W,
                                          const float* __restrict__ bias) {
    __shared__ __align__(16) float at[64][132];
    int t = threadIdx.x;
    int aBase = blockIdx.x * 128;
    int aCount = NATOM - aBase; if (aCount > 128) aCount = 128;

    float wreg[64];
    const float* wp = (t < 128) ? (W + t) : (W + 64 * TWOA + (t - 128));
    #pragma unroll
    for (int k = 0; k < 64; k++) wreg[k] = wp[k * TWOA];
    float bj = (t < 128) ? bias[t] : 0.0f;

    for (int idx = t; idx < 128 * 64; idx += 256) {
        int a = idx >> 6, k = idx & 63;
        at[k][a] = (a < aCount) ? atom[(size_t)(aBase + a) * AF + k] : 0.0f;
    }
    __syncthreads();

    float* dst = (t < 128) ? d_SW : d_PW;
    int j = t & 127;

    for (int c = 0; c < 16; c++) {
        int a0 = c * 8;
        ull acc[4] = {0ull, 0ull, 0ull, 0ull};
        #pragma unroll
        for (int k = 0; k < 64; k++) {
            ull wk = packdup(wreg[k]);
            const ull* ap = (const ull*)&at[k][a0];
            ffma2(acc[0], ap[0], wk);
            ffma2(acc[1], ap[1], wk);
            ffma2(acc[2], ap[2], wk);
            ffma2(acc[3], ap[3], wk);
        }
        #pragma unroll
        for (int q = 0; q < 4; q++) {
            float2 v = unpk(acc[q]);
            int a = a0 + 2 * q;
            if (a < aCount)     dst[(size_t)(aBase + a)     * TWOA + j] = v.x + bj;
            if (a + 1 < aCount) dst[(size_t)(aBase + a + 1) * TWOA + j] = v.y + bj;
        }
    }
}

// ---------------- kPack: d_PW -> half2 pair table d_PWf ----------------
__global__ void __launch_bounds__(256) kPack() {
    int id = blockIdx.x * 256 + threadIdx.x;     // NATOM*64 total
    int a = id >> 6, j = id & 63;
    float2 v = *(const float2*)(d_PW + (size_t)a * TWOA + 2 * j);
    __half2 h = __floats2half2_rn(v.x, v.y);
    d_PWf[id] = *(u32*)&h;
}

// ============ kGemmStore: persistent tf32 mma.sync; 768 thr = 24 warps ============
// warp w: rowTile rt=w%6 (rows 16rt..16rt+15), colEighth cE=w/6 (cols 32cE..32cE+31).
// K padded 41->48 (zeroed). gated stored in unchanged ull layout via smem staging.
__global__ void __launch_bounds__(768, 1) kGemmStore(const float* __restrict__ bond,
                                                     const int*   __restrict__ nidx,
                                                     const float* __restrict__ W,
                                                     const float* __restrict__ sc,
                                                     const float* __restrict__ of) {
    extern __shared__ __align__(16) char sm[];
    u32*   Ws   = (u32*)  (sm + OFF_WS);
    u32*   bT   = (u32*)  (sm + OFF_BT);
    float* braw = (float*)(sm + OFF_BRAW);
    u32*   stag = (u32*)  (sm + OFF_STAG);
    int*   idxS = (int*)  (sm + OFF_IDX);
    __shared__ int sLast;

    int t = threadIdx.x, lane = t & 31, w = t >> 5;
    int rt = w % 6, cE = w / 6;
    int g = lane >> 2, m = lane & 3;
    int row0 = 16 * rt + g, row1 = row0 + 8;
    int aL0 = row0 / 12, aL1 = row1 / 12;
    int colBase = 32 * cE + 2 * m;               // + 8n
    int lBase = 16 * (cE & 1) + m;               // + 4n
    int isC = (cE >= 2) ? 1 : 0;

    // ---- prolog ----
    {
        int t0 = blockIdx.x;
        const float* bsrc = bond + (size_t)t0 * 96 * BF;
        #pragma unroll
        for (int i = 0; i < 2; i++) {
            int c = t + 768 * i;
            if (c < 96 * BF / 4) cpasync16(braw + c * 4, bsrc + c * 4);
        }
        if (t < 24) {
            cpasync16(idxS + t * 4,      nidx + t0 * 96 + t * 4);
            cpasync16(idxS + 96 + t * 4, nidx + (t0 + PB) * 96 + t * 4);
        }
        const float* wsrc = W + TWOA * TWOA;     // W3 raw into stag temporarily
        #pragma unroll
        for (int i = 0; i < 2; i++) {
            int c = t + 768 * i;
            if (c < BF * TWOA / 4) cpasync16(stag + c * 4, wsrc + c * 4);
        }
        CP_COMMIT();
        CP_WAIT(0);
        __syncthreads();
        // cvt W3 -> Ws[48][136] tf32, zero pads
        for (int id = t; id < 48 * 136; id += 768) {
            int k = id / 136, n = id % 136;
            float v = (k < BF && n < TWOA) ? ((float*)stag)[k * TWOA + n] : 0.0f;
            Ws[id] = to_tf32(v);
        }
        // zero bT pad rows 41..47 (never rewritten)
        for (int id = t; id < 7 * 104; id += 768) bT[BF * 104 + id] = 0u;
        __syncthreads();
    }

    float ls0[4] = {0, 0, 0, 0}, ls1[4] = {0, 0, 0, 0};
    float lq0[4] = {0, 0, 0, 0}, lq1[4] = {0, 0, 0, 0};

    int n = 0, buf = 0;
    for (int tile = blockIdx.x; tile < NT; tile += PB, ++n, buf ^= 1) {
        CP_WAIT(0);
        __syncthreads();

        // transpose + cvt braw[buf][r][k] -> bT[k][r] (tf32)
        const float* bb = braw + buf * 3936;
        #pragma unroll
        for (int i = 0; i < 6; i++) {
            int id = t + 768 * i;
            if (id < 96 * BF) {
                int k = id / 96, r = id - 96 * k;
                bT[k * 104 + r] = to_tf32(bb[r * BF + k]);
            }
        }
        __syncthreads();

        // prefetch next tile bond + idx(n+2)
        {
            int nt = tile + PB;
            if (nt < NT) {
                const float* bsrc = bond + (size_t)nt * 96 * BF;
                #pragma unroll
                for (int i = 0; i < 2; i++) {
                    int c = t + 768 * i;
                    if (c < 96 * BF / 4) cpasync16(braw + (buf ^ 1) * 3936 + c * 4, bsrc + c * 4);
                }
                int nt2 = nt + PB;
                if (nt2 < NT && t < 24)
                    cpasync16(idxS + ((n + 2) % 3) * 96 + t * 4, nidx + nt2 * 96 + t * 4);
            }
            CP_COMMIT();
        }

        // ---- tf32 MMA: 6 k-steps x 4 n-tiles ----
        float acc[4][4];
        #pragma unroll
        for (int nn = 0; nn < 4; nn++)
            #pragma unroll
            for (int u = 0; u < 4; u++) acc[nn][u] = 0.0f;

        #pragma unroll
        for (int ks = 0; ks < 6; ks++) {
            const u32* bk = bT + (8 * ks + m) * 104;
            u32 a0 = bk[row0], a1 = bk[row1];
            u32 a2 = bk[4 * 104 + row0], a3 = bk[4 * 104 + row1];
            const u32* wk = Ws + (8 * ks + m) * 136;
            #pragma unroll
            for (int nn = 0; nn < 4; nn++) {
                int col = 32 * cE + 8 * nn + g;
                u32 b0 = wk[col], b1 = wk[4 * 136 + col];
                MMA_TF32(acc[nn], a0, a1, a2, a3, b0, b1);
            }
        }

        // ---- epilogue ----
        const int* idB = idxS + (n % 3) * 96;
        int i0 = idB[row0], i1 = idB[row1];
        size_t atom0 = (size_t)(tile * 8 + aL0), atom1 = (size_t)(tile * 8 + aL1);

        #pragma unroll
        for (int nn = 0; nn < 4; nn++) {
            int col = colBase + 8 * nn;          // global col, even
            float2 sw0 = __ldg((const float2*)(d_SW + atom0 * TWOA + col));
            float2 sw1 = __ldg((const float2*)(d_SW + atom1 * TWOA + col));
            u32 p0 = __ldg(d_PWf + (size_t)i0 * 64 + (col >> 1));
            u32 p1 = __ldg(d_PWf + (size_t)i1 * 64 + (col >> 1));
            float2 pw0 = __half22float2(*(__half2*)&p0);
            float2 pw1 = __half22float2(*(__half2*)&p1);
            float v00 = acc[nn][0] + sw0.x + pw0.x;
            float v01 = acc[nn][1] + sw0.y + pw0.y;
            float v10 = acc[nn][2] + sw1.x + pw1.x;
            float v11 = acc[nn][3] + sw1.y + pw1.y;
            ls0[nn] += v00 + v10;  lq0[nn] += v00 * v00 + v10 * v10;
            ls1[nn] += v01 + v11;  lq1[nn] += v01 * v01 + v11 * v11;
            __half2 h0 = __floats2half2_rn(v00, v01);
            __half2 h1 = __floats2half2_rn(v10, v11);
            int si = 2 * (lBase + 4 * nn) + isC;
            stag[row0 * 65 + si] = *(u32*)&h0;
            stag[row1 * 65 + si] = *(u32*)&h1;
        }
        __syncthreads();

        // coalesced gated store: ull[j] = {stag[r][2l], stag[r][2l+1]}
        ull* gb = d_gated16 + (size_t)tile * 96 * 32;
        #pragma unroll
        for (int i = 0; i < 4; i++) {
            int j = t + 768 * i;                 // 0..3071
            int r = j >> 5, l = j & 31;
            u32 lo = stag[r * 65 + 2 * l];
            u32 hi = stag[r * 65 + 2 * l + 1];
            __stcs(gb + j, (ull)lo | ((ull)hi << 32));
        }
    }

    // ---- stats: warp shfl-reduce then block reduce (overlay stag) ----
    __syncthreads();
    #pragma unroll
    for (int nn = 0; nn < 4; nn++) {
        #pragma unroll
        for (int s = 4; s <= 16; s <<= 1) {
            ls0[nn] += __shfl_xor_sync(0xffffffffu, ls0[nn], s);
            ls1[nn] += __shfl_xor_sync(0xffffffffu, ls1[nn], s);
            lq0[nn] += __shfl_xor_sync(0xffffffffu, lq0[nn], s);
            lq1[nn] += __shfl_xor_sync(0xffffffffu, lq1[nn], s);
        }
    }
    float* redS = (float*)(sm + OFF_RED);
    float* redQ = redS + 24 * 32;
    if (g == 0) {
        #pragma unroll
        for (int nn = 0; nn < 4; nn++) {
            int lc = 8 * nn + 2 * m;
            redS[w * 32 + lc] = ls0[nn];      redS[w * 32 + lc + 1] = ls1[nn];
            redQ[w * 32 + lc] = lq0[nn];      redQ[w * 32 + lc + 1] = lq1[nn];
        }
    }
    __syncthreads();
    if (t < TWOA) {
        int cEi = t >> 5, lc = t & 31;
        float s = 0.0f, q = 0.0f;
        #pragma unroll
        for (int r = 0; r < 6; r++) {
            s += redS[(cEi * 6 + r) * 32 + lc];
            q += redQ[(cEi * 6 + r) * 32 + lc];
        }
        atomicAdd(&d_s1[t], (double)s);
        atomicAdd(&d_q1[t], (double)q);
    }
    __syncthreads();
    if (t == 0) {
        __threadfence();
        unsigned old = atomicAdd(&d_c1, 1u);
        sLast = (old == PB - 1) ? 1 : 0;
    }
    __syncthreads();
    if (sLast && t < TWOA) {
        double s = *((volatile double*)&d_s1[t]);
        double q = *((volatile double*)&d_q1[t]);
        double mean = s / NMF;
        double var  = q / NMF - mean * mean;
        float gg = sc[t] * (float)(1.0 / sqrt(var + EPSBN));
        d_g1[t] = gg;
        d_h1[t] = of[t] - (float)mean * gg;
    }
}

// ---------------- kC: persistent; batched loads (MLP=6) per atom; BN2 stats in regs ----------
__global__ void __launch_bounds__(256) kC(const float* __restrict__ sc,
                                          const float* __restrict__ of) {
    __shared__ float rs[8][AF];
    __shared__ float rq[8][AF];
    __shared__ int sLast;
    int t = threadIdx.x;
    int lane = t & 31, w = t >> 5;
    int half = lane >> 4, q = lane & 15;
    int c0 = 4 * q;

    float4 G1A = *(const float4*)&d_g1[c0];
    float4 H1A = *(const float4*)&d_h1[c0];
    float4 G1B = *(const float4*)&d_g1[64 + c0];
    float4 H1B = *(const float4*)&d_h1[64 + c0];

    float as0 = 0, as1 = 0, as2 = 0, as3 = 0;
    float aq0 = 0, aq1 = 0, aq2 = 0, aq3 = 0;

    for (int tb = blockIdx.x; tb < NTC; tb += PB_C) {
        int aBase = tb * 32 + w * 4;
        #pragma unroll
        for (int u = 0; u < 4; u++) {
            int a = aBase + u;
            const uint4* gp = (const uint4*)(d_gated16 + (size_t)a * MNBR * 32);
            uint4 v[6];
            #pragma unroll
            for (int i = 0; i < 6; i++)
                v[i] = __ldcs(gp + (2 * i + half) * 16 + q);
            float s0 = 0.0f, s1 = 0.0f, s2 = 0.0f, s3 = 0.0f;
            #pragma unroll
            for (int i = 0; i < 6; i++) {
                float2 f01 = __half22float2(*(__half2*)&v[i].x);
                float2 c01 = __half22float2(*(__half2*)&v[i].y);
                float2 f23 = __half22float2(*(__half2*)&v[i].z);
                float2 c23 = __half22float2(*(__half2*)&v[i].w);
                float xf0 = f01.x * G1A.x + H1A.x;
                float xf1 = f01.y * G1A.y + H1A.y;
                float xf2 = f23.x * G1A.z + H1A.z;
                float xf3 = f23.y * G1A.w + H1A.w;
                float xc0 = c01.x * G1B.x + H1B.x;
                float xc1 = c01.y * G1B.y + H1B.y;
                float xc2 = c23.x * G1B.z + H1B.z;
                float xc3 = c23.y * G1B.w + H1B.w;
                s0 += sigmoidf_(xf0) * softplusf_(xc0);
                s1 += sigmoidf_(xf1) * softplusf_(xc1);
                s2 += sigmoidf_(xf2) * softplusf_(xc2);
                s3 += sigmoidf_(xf3) * softplusf_(xc3);
            }
            s0 += __shfl_xor_sync(0xffffffffu, s0, 16);
            s1 += __shfl_xor_sync(0xffffffffu, s1, 16);
            s2 += __shfl_xor_sync(0xffffffffu, s2, 16);
            s3 += __shfl_xor_sync(0xffffffffu, s3, 16);
            if (half == 0) {
                float4 sv; sv.x = s0; sv.y = s1; sv.z = s2; sv.w = s3;
                *(float4*)&d_summed[(size_t)a * AF + c0] = sv;
                as0 += s0; aq0 += s0 * s0;
                as1 += s1; aq1 += s1 * s1;
                as2 += s2; aq2 += s2 * s2;
                as3 += s3; aq3 += s3 * s3;
            }
        }
    }

    if (half == 0) {
        float4 sv; sv.x = as0; sv.y = as1; sv.z = as2; sv.w = as3;
        *(float4*)&rs[w][c0] = sv;
        float4 qv; qv.x = aq0; qv.y = aq1; qv.z = aq2; qv.w = aq3;
        *(float4*)&rq[w][c0] = qv;
    }
    __syncthreads();
    if (t < AF) {
        float s = 0.0f, qq = 0.0f;
        #pragma unroll
        for (int r = 0; r < 8; r++) { s += rs[r][t]; qq += rq[r][t]; }
        atomicAdd(&d_s2[t], (double)s);
        atomicAdd(&d_q2[t], (double)qq);
    }
    __syncthreads();
    if (t == 0) {
        __threadfence();
        unsigned old = atomicAdd(&d_c2, 1u);
        sLast = (old == PB_C - 1) ? 1 : 0;
    }
    __syncthreads();
    if (sLast && t < AF) {
        double s = *((volatile double*)&d_s2[t]);
        double qq = *((volatile double*)&d_q2[t]);
        double mean = s / NF;
        double var  = qq / NF - mean * mean;
        float g = sc[t] * (float)(1.0 / sqrt(var + EPSBN));
        d_g2[t] = g;
        d_h2[t] = of[t] - (float)mean * g;
    }
}

// ---------------- kD: out = softplus(atom + BN2(summed)) ----------------
__global__ void __launch_bounds__(256) kD(const float* __restrict__ atom,
                                          float* __restrict__ out) {
    int i = blockIdx.x * 256 + threadIdx.x;
    int c = i & (AF - 1);
    float y = d_summed[i] * d_g2[c] + d_h2[c];
    out[i] = softplusf_(atom[i] + y);
}

// ---------------- launch ----------------
extern "C" void kernel_launch(void* const* d_in, const int* in_sizes, int n_in,
                              void* d_out, int out_size) {
    const int*   nidx = (const int*)  d_in[0];
    const float* atom = (const float*)d_in[1];
    const float* bond = (const float*)d_in[2];
    const float* W    = (const float*)d_in[3];
    const float* bias = (const float*)d_in[4];
    const float* bn1s = (const float*)d_in[5];
    const float* bn1o = (const float*)d_in[6];
    const float* bn2s = (const float*)d_in[7];
    const float* bn2o = (const float*)d_in[8];
    float* out = (float*)d_out;

    cudaFuncSetAttribute(kGemmStore, cudaFuncAttributeMaxDynamicSharedMemorySize, SMEM_BYTES);

    kInit<<<1, 128>>>();                                                     // slot 1
    kA<<<(NATOM + 127) / 128, 256>>>(atom, W, bias);                         // slot 2
    kPack<<<(NATOM * 64) / 256, 256>>>();                                    // slot 3
    kGemmStore<<<PB, 768, SMEM_BYTES>>>(bond, nidx, W, bn1s, bn1o);          // slot 4 (ncu)
    kC<<<PB_C, 256>>>(bn2s, bn2o);                                           // slot 5
    kD<<<(NATOM * AF) / 256, 256>>>(atom, out);                              // slot 6
}